// round 2
// baseline (speedup 1.0000x reference)
#include <cuda_runtime.h>
#include <math.h>

#define NTOK 4096
#define NPAD 4097
#define DIM 512
#define HEADS 8
#define DH 64
#define MM 17
#define LBLK 241            // NPAD / MM
#define QKVD 1536
#define KCONV 33
#define OUT1_SIZE (NTOK*DIM)          // 2097152
#define ATTN_PER_HEAD ((size_t)NPAD*NPAD)

// ---------------- scratch (static device memory; no allocations) ----------
__device__ float g_xp[NPAD*DIM];          // padded layernorm output (row 0 = 0)
__device__ float g_qkv[NPAD*QKVD];        // qkv, q already scaled by 1/8
__device__ float g_ql[HEADS*MM*DH];
__device__ float g_kl[HEADS*MM*DH];
__device__ float g_attn1[HEADS*NPAD*MM];
__device__ float g_attn3[HEADS*MM*NPAD];
__device__ float g_inv[HEADS*MM*MM];
__device__ float g_av[HEADS*MM*DH];       // attn3 @ v
__device__ float g_w1[HEADS*NPAD*MM];     // attn1 @ attn2_inv
__device__ float g_outh[NPAD*DIM];        // heads merged back, [t][h*64+d]

// ---------------- 1. LayerNorm into padded buffer --------------------------
__global__ void ln_kernel(const float* __restrict__ x,
                          const float* __restrict__ w,
                          const float* __restrict__ b) {
    int r = blockIdx.x;               // 0..NPAD-1 ; row 0 is the zero pad
    int tid = threadIdx.x;
    if (r == 0) {
        for (int c = tid; c < DIM; c += 256) g_xp[c] = 0.f;
        return;
    }
    const float* row = x + (size_t)(r-1)*DIM;
    __shared__ float red[256];
    float s = 0.f;
    for (int c = tid; c < DIM; c += 256) s += row[c];
    red[tid] = s; __syncthreads();
    for (int o = 128; o; o >>= 1) { if (tid < o) red[tid] += red[tid+o]; __syncthreads(); }
    float mu = red[0] * (1.0f/DIM);
    __syncthreads();
    float v = 0.f;
    for (int c = tid; c < DIM; c += 256) { float d = row[c]-mu; v += d*d; }
    red[tid] = v; __syncthreads();
    for (int o = 128; o; o >>= 1) { if (tid < o) red[tid] += red[tid+o]; __syncthreads(); }
    float rs = rsqrtf(red[0]*(1.0f/DIM) + 1e-5f);
    for (int c = tid; c < DIM; c += 256)
        g_xp[(size_t)r*DIM + c] = (row[c]-mu)*rs*w[c] + b[c];
}

// ---------------- 2/10. Tiled fp32 GEMM: C = A(MxK) @ B^T (B is NxK) -------
// mode 0: scale first 512 cols by 0.125 (q scaling)  -> C row stride N
// mode 1: C = acc + bias[c] + resid[r*N+c]
#define BM 128
#define BN 128
#define BK 8
__global__ __launch_bounds__(256)
void gemm_abT(const float* __restrict__ A, const float* __restrict__ B,
              float* __restrict__ C, int M, int N, int K, int mode,
              const float* __restrict__ bias, const float* __restrict__ resid) {
    __shared__ float As[BK][BM+4];
    __shared__ float Bs[BK][BN+4];
    int tid = threadIdx.x;
    int tx = tid & 15, ty = tid >> 4;
    int row0 = blockIdx.y * BM, col0 = blockIdx.x * BN;
    int lRow = tid >> 1;            // 0..127
    int lK   = (tid & 1) * 4;       // 0 or 4
    float acc[8][8] = {};
    for (int k0 = 0; k0 < K; k0 += BK) {
        int gr = row0 + lRow;
        float4 a4 = make_float4(0,0,0,0);
        if (gr < M) a4 = *(const float4*)(A + (size_t)gr*K + k0 + lK);
        As[lK+0][lRow]=a4.x; As[lK+1][lRow]=a4.y; As[lK+2][lRow]=a4.z; As[lK+3][lRow]=a4.w;
        int gc = col0 + lRow;
        float4 b4 = make_float4(0,0,0,0);
        if (gc < N) b4 = *(const float4*)(B + (size_t)gc*K + k0 + lK);
        Bs[lK+0][lRow]=b4.x; Bs[lK+1][lRow]=b4.y; Bs[lK+2][lRow]=b4.z; Bs[lK+3][lRow]=b4.w;
        __syncthreads();
        #pragma unroll
        for (int k = 0; k < BK; k++) {
            float ra[8], rb[8];
            *(float4*)(ra)   = *(const float4*)&As[k][ty*8];
            *(float4*)(ra+4) = *(const float4*)&As[k][ty*8+4];
            *(float4*)(rb)   = *(const float4*)&Bs[k][tx*8];
            *(float4*)(rb+4) = *(const float4*)&Bs[k][tx*8+4];
            #pragma unroll
            for (int i = 0; i < 8; i++)
                #pragma unroll
                for (int j = 0; j < 8; j++)
                    acc[i][j] += ra[i]*rb[j];
        }
        __syncthreads();
    }
    #pragma unroll
    for (int i = 0; i < 8; i++) {
        int r = row0 + ty*8 + i;
        if (r >= M) continue;
        #pragma unroll
        for (int j = 0; j < 8; j++) {
            int c = col0 + tx*8 + j;
            if (c >= N) continue;
            float v = acc[i][j];
            if (mode == 0) {
                if (c < 512) v *= 0.125f;
                C[(size_t)r*N + c] = v;
            } else {
                C[(size_t)r*N + c] = v + bias[c] + resid[(size_t)r*N + c];
            }
        }
    }
}

// ---------------- 3. landmarks: mean of LBLK consecutive tokens ------------
__global__ void landmark_kernel() {
    int m = blockIdx.x, h = blockIdx.y, which = blockIdx.z; // 0=q, 1=k
    int d = threadIdx.x;
    int base = which ? 512 : 0;
    float s = 0.f;
    const float* p = g_qkv + (size_t)(m*LBLK)*QKVD + base + h*DH + d;
    for (int i = 0; i < LBLK; i++) s += p[(size_t)i*QKVD];
    float v = s * (1.0f/LBLK);
    if (which) g_kl[(h*MM+m)*DH + d] = v; else g_ql[(h*MM+m)*DH + d] = v;
}

// ---------------- 4. attn1 = softmax(q @ k_l^T), 17-wide ------------------
__global__ void attn1_kernel() {
    int gw = (blockIdx.x*blockDim.x + threadIdx.x) >> 5;
    int lane = threadIdx.x & 31;
    if (gw >= HEADS*NPAD) return;
    int h = gw / NPAD, t = gw % NPAD;
    const float* q = g_qkv + (size_t)t*QKVD + h*DH;
    float dot = -INFINITY;
    if (lane < MM) {
        const float* kl = g_kl + (h*MM + lane)*DH;
        float s = 0.f;
        #pragma unroll
        for (int d = 0; d < DH; d += 4) {
            float4 qa = *(const float4*)(q + d);
            float4 ka = *(const float4*)(kl + d);
            s += qa.x*ka.x + qa.y*ka.y + qa.z*ka.z + qa.w*ka.w;
        }
        dot = s;
    }
    float mx = dot;
    #pragma unroll
    for (int o = 16; o; o >>= 1) mx = fmaxf(mx, __shfl_xor_sync(0xffffffffu, mx, o));
    float e = (lane < MM) ? expf(dot - mx) : 0.f;
    float sum = e;
    #pragma unroll
    for (int o = 16; o; o >>= 1) sum += __shfl_xor_sync(0xffffffffu, sum, o);
    if (lane < MM) g_attn1[((size_t)h*NPAD + t)*MM + lane] = e / sum;
}

// ---------------- 5. attn2 softmax + Moore-Penrose pinv (17x17) ------------
__global__ void pinv_kernel() {
    int h = blockIdx.x;
    int tid = threadIdx.x;          // 289 threads
    int i = tid / MM, j = tid % MM;
    __shared__ float a[MM][MM], z[MM][MM], az[MM][MM], t1[MM][MM], t2[MM][MM];
    __shared__ float sc;
    // logits
    {
        const float* ql = g_ql + (h*MM + i)*DH;
        const float* kl = g_kl + (h*MM + j)*DH;
        float s = 0.f;
        #pragma unroll
        for (int d = 0; d < DH; d++) s += ql[d]*kl[d];
        a[i][j] = s;
    }
    __syncthreads();
    if (tid < MM) { // row softmax
        float mx = -INFINITY;
        for (int c = 0; c < MM; c++) mx = fmaxf(mx, a[tid][c]);
        float s = 0.f;
        for (int c = 0; c < MM; c++) { float e = expf(a[tid][c]-mx); a[tid][c] = e; s += e; }
        float inv = 1.f/s;
        for (int c = 0; c < MM; c++) a[tid][c] *= inv;
    }
    __syncthreads();
    if (tid == 0) {
        float col = 0.f, row = 0.f;
        for (int r = 0; r < MM; r++) { float s = 0.f; for (int c = 0; c < MM; c++) s += fabsf(a[r][c]); col = fmaxf(col, s); }
        for (int c = 0; c < MM; c++) { float s = 0.f; for (int r = 0; r < MM; r++) s += fabsf(a[r][c]); row = fmaxf(row, s); }
        sc = 1.f/(col*row);
    }
    __syncthreads();
    z[i][j] = a[j][i] * sc;
    __syncthreads();
    for (int it = 0; it < 6; it++) {
        float s = 0.f;
        for (int k = 0; k < MM; k++) s += a[i][k]*z[k][j];
        az[i][j] = s; __syncthreads();
        t1[i][j] = (i==j ? 7.f : 0.f) - az[i][j]; __syncthreads();
        s = 0.f;
        for (int k = 0; k < MM; k++) s += az[i][k]*t1[k][j];
        t2[i][j] = s; __syncthreads();
        t2[i][j] = (i==j ? 15.f : 0.f) - t2[i][j]; __syncthreads();
        s = 0.f;
        for (int k = 0; k < MM; k++) s += az[i][k]*t2[k][j];
        t1[i][j] = s; __syncthreads();
        t1[i][j] = (i==j ? 13.f : 0.f) - t1[i][j]; __syncthreads();
        s = 0.f;
        for (int k = 0; k < MM; k++) s += z[i][k]*t1[k][j];
        t2[i][j] = 0.25f*s; __syncthreads();
        z[i][j] = t2[i][j]; __syncthreads();
    }
    g_inv[(h*MM + i)*MM + j] = z[i][j];
}

// ---------------- 6. attn3 = softmax(q_l @ k^T), 4097-wide ----------------
__global__ void attn3_kernel() {
    int m = blockIdx.x, h = blockIdx.y;
    int tid = threadIdx.x;          // 256
    __shared__ float sl[NPAD];
    __shared__ float qs[DH];
    __shared__ float red[256];
    if (tid < DH) qs[tid] = g_ql[(h*MM+m)*DH + tid];
    __syncthreads();
    float lmax = -INFINITY;
    for (int t = tid; t < NPAD; t += 256) {
        const float* kp = g_qkv + (size_t)t*QKVD + 512 + h*DH;
        float s = 0.f;
        #pragma unroll
        for (int d = 0; d < DH; d += 4) {
            float4 kv = *(const float4*)(kp + d);
            s += qs[d]*kv.x + qs[d+1]*kv.y + qs[d+2]*kv.z + qs[d+3]*kv.w;
        }
        sl[t] = s;
        lmax = fmaxf(lmax, s);
    }
    red[tid] = lmax; __syncthreads();
    for (int o = 128; o; o >>= 1) { if (tid < o) red[tid] = fmaxf(red[tid], red[tid+o]); __syncthreads(); }
    float mx = red[0];
    __syncthreads();
    float lsum = 0.f;
    for (int t = tid; t < NPAD; t += 256) { float e = expf(sl[t]-mx); sl[t] = e; lsum += e; }
    red[tid] = lsum; __syncthreads();
    for (int o = 128; o; o >>= 1) { if (tid < o) red[tid] += red[tid+o]; __syncthreads(); }
    float inv = 1.f / red[0];
    for (int t = tid; t < NPAD; t += 256)
        g_attn3[((size_t)h*MM + m)*NPAD + t] = sl[t]*inv;
}

// ---------------- 7. av = attn3 @ v ----------------------------------------
__global__ void av_kernel() {
    int m = blockIdx.x, h = blockIdx.y;
    int tid = threadIdx.x;          // 256 = 4 groups x 64 d
    int d = tid & 63, g = tid >> 6;
    const float* arow = g_attn3 + ((size_t)h*MM + m)*NPAD;
    float acc = 0.f;
    for (int t = g; t < NPAD; t += 4)
        acc += arow[t] * g_qkv[(size_t)t*QKVD + 1024 + h*DH + d];
    __shared__ float part[256];
    part[tid] = acc; __syncthreads();
    if (tid < 64)
        g_av[(h*MM+m)*DH + tid] = part[tid] + part[tid+64] + part[tid+128] + part[tid+192];
}

// ---------------- 8a. w1 = attn1 @ attn2_inv -------------------------------
__global__ void w1_kernel() {
    size_t idx = (size_t)blockIdx.x*blockDim.x + threadIdx.x;
    size_t total = (size_t)HEADS*NPAD*MM;
    if (idx >= total) return;
    int j = idx % MM;
    size_t ht = idx / MM;
    int t = ht % NPAD, h = ht / NPAD;
    const float* a1 = g_attn1 + ((size_t)h*NPAD + t)*MM;
    const float* iv = g_inv + h*MM*MM;
    float s = 0.f;
    #pragma unroll
    for (int k = 0; k < MM; k++) s += a1[k]*iv[k*MM + j];
    g_w1[((size_t)h*NPAD + t)*MM + j] = s;
}

// ---------------- 8b. out_heads = w1 @ av + depthwise conv(v) --------------
__global__ void outh_kernel(const float* __restrict__ conv_w) {
    int t = blockIdx.x, h = blockIdx.y;
    int d = threadIdx.x;            // 64
    const float* w1 = g_w1 + ((size_t)h*NPAD + t)*MM;
    float acc = 0.f;
    #pragma unroll
    for (int m = 0; m < MM; m++) acc += w1[m]*g_av[(h*MM+m)*DH + d];
    const float* cw = conv_w + h*KCONV;
    #pragma unroll
    for (int k = 0; k < KCONV; k++) {
        int tt = t + k - (KCONV/2);
        if (tt >= 0 && tt < NPAD)
            acc += cw[k]*g_qkv[(size_t)tt*QKVD + 1024 + h*DH + d];
    }
    g_outh[(size_t)t*DIM + h*DH + d] = acc;
}

// ---------------- 11. attn = w1 @ attn3 -> 537 MB output -------------------
__global__ __launch_bounds__(128)
void attn_final_kernel(float* __restrict__ out) {
    int h = blockIdx.z;
    int t0 = blockIdx.y * 32;
    int s = blockIdx.x * 128 + threadIdx.x;
    __shared__ float w1s[32][20];   // padded rows, 16B aligned
    for (int idx = threadIdx.x; idx < 32*MM; idx += 128) {
        int r = idx / MM, m = idx % MM;
        int t = t0 + r;
        w1s[r][m] = (t < NPAD) ? g_w1[((size_t)h*NPAD + t)*MM + m] : 0.f;
    }
    float a3[MM];
    if (s < NPAD) {
        #pragma unroll
        for (int m = 0; m < MM; m++) a3[m] = g_attn3[((size_t)h*MM + m)*NPAD + s];
    }
    __syncthreads();
    if (s >= NPAD) return;
    float* base = out + (size_t)h*ATTN_PER_HEAD + (size_t)t0*NPAD + s;
    int rmax = min(32, NPAD - t0);
    for (int r = 0; r < rmax; r++) {
        float4 wa = *(const float4*)&w1s[r][0];
        float4 wb = *(const float4*)&w1s[r][4];
        float4 wc = *(const float4*)&w1s[r][8];
        float4 wd = *(const float4*)&w1s[r][12];
        float w16 = w1s[r][16];
        float acc = wa.x*a3[0] + wa.y*a3[1] + wa.z*a3[2] + wa.w*a3[3]
                  + wb.x*a3[4] + wb.y*a3[5] + wb.z*a3[6] + wb.w*a3[7]
                  + wc.x*a3[8] + wc.y*a3[9] + wc.z*a3[10] + wc.w*a3[11]
                  + wd.x*a3[12]+ wd.y*a3[13]+ wd.z*a3[14]+ wd.w*a3[15]
                  + w16*a3[16];
        base[(size_t)r*NPAD] = acc;
    }
}

// ---------------- launch ----------------------------------------------------
extern "C" void kernel_launch(void* const* d_in, const int* in_sizes, int n_in,
                              void* d_out, int out_size) {
    const float* x      = (const float*)d_in[0];
    const float* norm_w = (const float*)d_in[1];
    const float* norm_b = (const float*)d_in[2];
    const float* w_qkv  = (const float*)d_in[3];
    const float* w_out  = (const float*)d_in[4];
    const float* b_out  = (const float*)d_in[5];
    const float* conv_w = (const float*)d_in[6];
    float* out = (float*)d_out;

    float *p_xp, *p_qkv, *p_outh;
    cudaGetSymbolAddress((void**)&p_xp,   g_xp);
    cudaGetSymbolAddress((void**)&p_qkv,  g_qkv);
    cudaGetSymbolAddress((void**)&p_outh, g_outh);

    // 1. LayerNorm (+ zero pad row 0)
    ln_kernel<<<NPAD, 256>>>(x, norm_w, norm_b);
    // 2. QKV GEMM: [4097,1536] = xp[4097,512] @ w_qkv^T, q scaled by 0.125
    gemm_abT<<<dim3(QKVD/BN, (NPAD+BM-1)/BM), 256>>>(p_xp, w_qkv, p_qkv,
                                                     NPAD, QKVD, DIM, 0, nullptr, nullptr);
    // 3. landmarks
    landmark_kernel<<<dim3(MM, HEADS, 2), DH>>>();
    // 4. attn1
    attn1_kernel<<<(HEADS*NPAD*32 + 127)/128, 128>>>();
    // 5. attn2 + pinv
    pinv_kernel<<<HEADS, MM*MM>>>();
    // 6. attn3
    attn3_kernel<<<dim3(MM, HEADS), 256>>>();
    // 7. av = attn3 @ v
    av_kernel<<<dim3(MM, HEADS), 256>>>();
    // 8a. w1 = attn1 @ pinv
    w1_kernel<<<(HEADS*NPAD*MM + 255)/256, 256>>>();
    // 8b. out_heads = w1 @ av + conv
    outh_kernel<<<dim3(NPAD, HEADS), DH>>>(conv_w);
    // 10. final projection + bias + residual (rows 1..4096 of out_heads)
    gemm_abT<<<dim3(DIM/BN, NTOK/BM), 256>>>(p_outh + DIM, w_out, out,
                                             NTOK, DIM, DIM, 1, b_out, x);
    // 11. attn = w1 @ attn3 (big write)
    attn_final_kernel<<<dim3((NPAD+127)/128, (NPAD+31)/32, HEADS), 128>>>(out + OUT1_SIZE);
}

// round 3
// speedup vs baseline: 1.3432x; 1.3432x over previous
#include <cuda_runtime.h>
#include <math.h>

#define NTOK 4096
#define NPAD 4097
#define DIM 512
#define HEADS 8
#define DH 64
#define MM 17
#define LBLK 241
#define QKVD 1536
#define KCONV 33
#define OUT1_SIZE (NTOK*DIM)
#define ATTN_PER_HEAD ((size_t)NPAD*NPAD)
#define AVCH 8   // av token chunks

// ---------------- scratch ---------------------------------------------------
__device__ float g_xp[NPAD*DIM];
__device__ float g_qkv[NPAD*QKVD];        // q scaled by 1/8
__device__ float g_ql[HEADS*MM*DH];
__device__ float g_kl[HEADS*MM*DH];
__device__ float g_attn3[HEADS*MM*NPAD];  // logits, then normalized in place
__device__ float g_inv[HEADS*MM*MM];
__device__ float g_avp[AVCH*HEADS*MM*DH]; // av partials per chunk
__device__ float g_w1[HEADS*NPAD*MM];     // attn1 @ pinv
__device__ float g_outh[NPAD*DIM];

// ---------------- 1. LayerNorm ----------------------------------------------
__global__ void ln_kernel(const float* __restrict__ x,
                          const float* __restrict__ w,
                          const float* __restrict__ b) {
    int r = blockIdx.x;
    int tid = threadIdx.x;
    if (r == 0) { for (int c = tid; c < DIM; c += 256) g_xp[c] = 0.f; return; }
    const float* row = x + (size_t)(r-1)*DIM;
    __shared__ float red[256];
    float s = 0.f;
    for (int c = tid; c < DIM; c += 256) s += row[c];
    red[tid] = s; __syncthreads();
    for (int o = 128; o; o >>= 1) { if (tid < o) red[tid] += red[tid+o]; __syncthreads(); }
    float mu = red[0] * (1.0f/DIM);
    __syncthreads();
    float v = 0.f;
    for (int c = tid; c < DIM; c += 256) { float d = row[c]-mu; v += d*d; }
    red[tid] = v; __syncthreads();
    for (int o = 128; o; o >>= 1) { if (tid < o) red[tid] += red[tid+o]; __syncthreads(); }
    float rs = rsqrtf(red[0]*(1.0f/DIM) + 1e-5f);
    for (int c = tid; c < DIM; c += 256)
        g_xp[(size_t)r*DIM + c] = (row[c]-mu)*rs*w[c] + b[c];
}

// ---------------- GEMM: C = A(MxK) @ B^T, BK=16, double-buffered ------------
#define BM 128
#define BN 128
#define BK 16
__global__ __launch_bounds__(256)
void gemm_abT(const float* __restrict__ A, const float* __restrict__ B,
              float* __restrict__ C, int M, int N, int K, int mode,
              const float* __restrict__ bias, const float* __restrict__ resid) {
    __shared__ float As[2][BK][BM+4];
    __shared__ float Bs[2][BK][BN+4];
    int tid = threadIdx.x;
    int tx = tid & 15, ty = tid >> 4;
    int row0 = blockIdx.y * BM, col0 = blockIdx.x * BN;
    float acc[8][8] = {};
    float4 fa[2], fb[2];

    // prefetch tile 0 straight to smem
    #pragma unroll
    for (int u = 0; u < 2; u++) {
        int idx = tid*2 + u; int row = idx >> 2; int c4 = idx & 3;
        int gr = row0 + row;
        float4 a4 = (gr < M) ? *(const float4*)(A + (size_t)gr*K + c4*4)
                             : make_float4(0,0,0,0);
        As[0][c4*4+0][row]=a4.x; As[0][c4*4+1][row]=a4.y;
        As[0][c4*4+2][row]=a4.z; As[0][c4*4+3][row]=a4.w;
        int gc = col0 + row;
        float4 b4 = (gc < N) ? *(const float4*)(B + (size_t)gc*K + c4*4)
                             : make_float4(0,0,0,0);
        Bs[0][c4*4+0][row]=b4.x; Bs[0][c4*4+1][row]=b4.y;
        Bs[0][c4*4+2][row]=b4.z; Bs[0][c4*4+3][row]=b4.w;
    }
    __syncthreads();

    int nt = K / BK;
    for (int t = 0; t < nt; t++) {
        int cur = t & 1, nxt = cur ^ 1;
        if (t + 1 < nt) {
            int k0 = (t+1) * BK;
            #pragma unroll
            for (int u = 0; u < 2; u++) {
                int idx = tid*2 + u; int row = idx >> 2; int c4 = idx & 3;
                int gr = row0 + row;
                fa[u] = (gr < M) ? *(const float4*)(A + (size_t)gr*K + k0 + c4*4)
                                 : make_float4(0,0,0,0);
                int gc = col0 + row;
                fb[u] = (gc < N) ? *(const float4*)(B + (size_t)gc*K + k0 + c4*4)
                                 : make_float4(0,0,0,0);
            }
        }
        #pragma unroll
        for (int k = 0; k < BK; k++) {
            float ra[8], rb[8];
            *(float4*)(ra)   = *(const float4*)&As[cur][k][ty*8];
            *(float4*)(ra+4) = *(const float4*)&As[cur][k][ty*8+4];
            *(float4*)(rb)   = *(const float4*)&Bs[cur][k][tx*8];
            *(float4*)(rb+4) = *(const float4*)&Bs[cur][k][tx*8+4];
            #pragma unroll
            for (int i = 0; i < 8; i++)
                #pragma unroll
                for (int j = 0; j < 8; j++)
                    acc[i][j] += ra[i]*rb[j];
        }
        if (t + 1 < nt) {
            #pragma unroll
            for (int u = 0; u < 2; u++) {
                int idx = tid*2 + u; int row = idx >> 2; int c4 = idx & 3;
                As[nxt][c4*4+0][row]=fa[u].x; As[nxt][c4*4+1][row]=fa[u].y;
                As[nxt][c4*4+2][row]=fa[u].z; As[nxt][c4*4+3][row]=fa[u].w;
                Bs[nxt][c4*4+0][row]=fb[u].x; Bs[nxt][c4*4+1][row]=fb[u].y;
                Bs[nxt][c4*4+2][row]=fb[u].z; Bs[nxt][c4*4+3][row]=fb[u].w;
            }
        }
        __syncthreads();
    }
    #pragma unroll
    for (int i = 0; i < 8; i++) {
        int r = row0 + ty*8 + i;
        if (r >= M) continue;
        #pragma unroll
        for (int j = 0; j < 8; j++) {
            int c = col0 + tx*8 + j;
            if (c >= N) continue;
            float v = acc[i][j];
            if (mode == 0) {
                if (c < 512) v *= 0.125f;
                C[(size_t)r*N + c] = v;
            } else {
                C[(size_t)r*N + c] = v + bias[c] + resid[(size_t)r*N + c];
            }
        }
    }
}

// ---------------- 3. landmarks (coalesced column sums) ----------------------
__global__ void landmark_kernel() {
    int m = blockIdx.x, which = blockIdx.y;   // 0=q, 1=k
    int c = threadIdx.x;                      // 0..511
    int base = which ? 512 : 0;
    const float* p = g_qkv + (size_t)(m*LBLK)*QKVD + base + c;
    float s = 0.f;
    for (int i = 0; i < LBLK; i++) s += p[(size_t)i*QKVD];
    float v = s * (1.0f/LBLK);
    int h = c >> 6, d = c & 63;
    if (which) g_kl[(h*MM+m)*DH + d] = v; else g_ql[(h*MM+m)*DH + d] = v;
}

// ---------------- 5. attn2 softmax + pinv (17x17) ---------------------------
__global__ void pinv_kernel() {
    int h = blockIdx.x;
    int tid = threadIdx.x;          // 289
    int i = tid / MM, j = tid % MM;
    __shared__ float a[MM][MM], z[MM][MM], az[MM][MM], t1[MM][MM], t2[MM][MM];
    __shared__ float sc;
    {
        const float* ql = g_ql + (h*MM + i)*DH;
        const float* kl = g_kl + (h*MM + j)*DH;
        float s = 0.f;
        #pragma unroll
        for (int d = 0; d < DH; d++) s += ql[d]*kl[d];
        a[i][j] = s;
    }
    __syncthreads();
    if (tid < MM) {
        float mx = -INFINITY;
        for (int c = 0; c < MM; c++) mx = fmaxf(mx, a[tid][c]);
        float s = 0.f;
        for (int c = 0; c < MM; c++) { float e = expf(a[tid][c]-mx); a[tid][c] = e; s += e; }
        float inv = 1.f/s;
        for (int c = 0; c < MM; c++) a[tid][c] *= inv;
    }
    __syncthreads();
    if (tid == 0) {
        float col = 0.f, row = 0.f;
        for (int r = 0; r < MM; r++) { float s = 0.f; for (int c = 0; c < MM; c++) s += fabsf(a[r][c]); col = fmaxf(col, s); }
        for (int c = 0; c < MM; c++) { float s = 0.f; for (int r = 0; r < MM; r++) s += fabsf(a[r][c]); row = fmaxf(row, s); }
        sc = 1.f/(col*row);
    }
    __syncthreads();
    z[i][j] = a[j][i] * sc;
    __syncthreads();
    for (int it = 0; it < 6; it++) {
        float s = 0.f;
        for (int k = 0; k < MM; k++) s += a[i][k]*z[k][j];
        az[i][j] = s; __syncthreads();
        t1[i][j] = (i==j ? 7.f : 0.f) - az[i][j]; __syncthreads();
        s = 0.f;
        for (int k = 0; k < MM; k++) s += az[i][k]*t1[k][j];
        t2[i][j] = s; __syncthreads();
        t2[i][j] = (i==j ? 15.f : 0.f) - t2[i][j]; __syncthreads();
        s = 0.f;
        for (int k = 0; k < MM; k++) s += az[i][k]*t2[k][j];
        t1[i][j] = s; __syncthreads();
        t1[i][j] = (i==j ? 13.f : 0.f) - t1[i][j]; __syncthreads();
        s = 0.f;
        for (int k = 0; k < MM; k++) s += z[i][k]*t1[k][j];
        t2[i][j] = 0.25f*s; __syncthreads();
        z[i][j] = t2[i][j]; __syncthreads();
    }
    g_inv[(h*MM + i)*MM + j] = z[i][j];
}

// ---------------- 4+8a fused: w1 = softmax(q @ kl^T) @ inv ------------------
#define QS 68
__global__ __launch_bounds__(128)
void attn1w1_kernel() {
    int h = blockIdx.y;
    int t0 = blockIdx.x * 128;
    int tid = threadIdx.x;
    __shared__ float qs[128][QS];
    __shared__ float kls[MM*DH];
    __shared__ float invs[MM*MM];
    // stage q tile (coalesced)
    #pragma unroll
    for (int i = 0; i < 16; i++) {
        int idx = i*128 + tid;
        int row = idx >> 4, c4 = idx & 15;
        int gt = t0 + row;
        float4 v = (gt < NPAD) ? *(const float4*)&g_qkv[(size_t)gt*QKVD + h*DH + c4*4]
                               : make_float4(0,0,0,0);
        *(float4*)&qs[row][c4*4] = v;
    }
    for (int idx = tid; idx < MM*DH; idx += 128) kls[idx] = g_kl[h*MM*DH + idx];
    for (int idx = tid; idx < MM*MM; idx += 128) invs[idx] = g_inv[h*MM*MM + idx];
    __syncthreads();
    int t = t0 + tid;
    if (t >= NPAD) return;
    float lg[MM];
    #pragma unroll
    for (int m = 0; m < MM; m++) lg[m] = 0.f;
    #pragma unroll
    for (int d4 = 0; d4 < 16; d4++) {
        float4 q4 = *(const float4*)&qs[tid][d4*4];
        #pragma unroll
        for (int m = 0; m < MM; m++) {
            float4 k4 = *(const float4*)&kls[m*DH + d4*4];
            lg[m] += q4.x*k4.x + q4.y*k4.y + q4.z*k4.z + q4.w*k4.w;
        }
    }
    float mx = lg[0];
    #pragma unroll
    for (int m = 1; m < MM; m++) mx = fmaxf(mx, lg[m]);
    float sum = 0.f;
    #pragma unroll
    for (int m = 0; m < MM; m++) { lg[m] = expf(lg[m]-mx); sum += lg[m]; }
    float inv = 1.f/sum;
    #pragma unroll
    for (int m = 0; m < MM; m++) lg[m] *= inv;
    float* wout = g_w1 + ((size_t)h*NPAD + t)*MM;
    #pragma unroll
    for (int j = 0; j < MM; j++) {
        float s = 0.f;
        #pragma unroll
        for (int k = 0; k < MM; k++) s += lg[k]*invs[k*MM + j];
        wout[j] = s;
    }
}

// ---------------- 6a. attn3 logits (k staged once) --------------------------
__global__ __launch_bounds__(128)
void attn3a_kernel() {
    int h = blockIdx.y;
    int t0 = blockIdx.x * 128;
    int tid = threadIdx.x;
    __shared__ float ks[128][QS];
    __shared__ float qls[MM*DH];
    #pragma unroll
    for (int i = 0; i < 16; i++) {
        int idx = i*128 + tid;
        int row = idx >> 4, c4 = idx & 15;
        int gt = t0 + row;
        float4 v = (gt < NPAD) ? *(const float4*)&g_qkv[(size_t)gt*QKVD + 512 + h*DH + c4*4]
                               : make_float4(0,0,0,0);
        *(float4*)&ks[row][c4*4] = v;
    }
    for (int idx = tid; idx < MM*DH; idx += 128) qls[idx] = g_ql[h*MM*DH + idx];
    __syncthreads();
    int t = t0 + tid;
    if (t >= NPAD) return;
    float lg[MM];
    #pragma unroll
    for (int m = 0; m < MM; m++) lg[m] = 0.f;
    #pragma unroll
    for (int d4 = 0; d4 < 16; d4++) {
        float4 k4 = *(const float4*)&ks[tid][d4*4];
        #pragma unroll
        for (int m = 0; m < MM; m++) {
            float4 q4 = *(const float4*)&qls[m*DH + d4*4];
            lg[m] += q4.x*k4.x + q4.y*k4.y + q4.z*k4.z + q4.w*k4.w;
        }
    }
    #pragma unroll
    for (int m = 0; m < MM; m++)
        g_attn3[((size_t)h*MM + m)*NPAD + t] = lg[m];
}

// ---------------- 6b. attn3 softmax normalize (per h,m row) -----------------
__global__ void attn3b_kernel() {
    int m = blockIdx.x, h = blockIdx.y;
    int tid = threadIdx.x;          // 256
    __shared__ float buf[NPAD];
    __shared__ float red[256];
    float* rowp = g_attn3 + ((size_t)h*MM + m)*NPAD;
    float lmax = -INFINITY;
    for (int t = tid; t < NPAD; t += 256) { float v = rowp[t]; buf[t] = v; lmax = fmaxf(lmax, v); }
    red[tid] = lmax; __syncthreads();
    for (int o = 128; o; o >>= 1) { if (tid < o) red[tid] = fmaxf(red[tid], red[tid+o]); __syncthreads(); }
    float mx = red[0];
    __syncthreads();
    float lsum = 0.f;
    for (int t = tid; t < NPAD; t += 256) { float e = expf(buf[t]-mx); buf[t] = e; lsum += e; }
    red[tid] = lsum; __syncthreads();
    for (int o = 128; o; o >>= 1) { if (tid < o) red[tid] += red[tid+o]; __syncthreads(); }
    float inv = 1.f / red[0];
    for (int t = tid; t < NPAD; t += 256) rowp[t] = buf[t]*inv;
}

// ---------------- 7. av partials: av = attn3 @ v (v staged once) ------------
__global__ __launch_bounds__(544)
void av_kernel() {
    int ch = blockIdx.x, h = blockIdx.y;
    int tid = threadIdx.x;          // 544 = 17 warps
    int m = tid >> 5, lane = tid & 31;
    int start = ch * 512;
    int end = min(start + 512, NPAD);
    __shared__ float vs[32][QS];
    __shared__ float a3s[MM][32];
    float2 acc = make_float2(0.f, 0.f);
    int nsub = (end - start + 31) >> 5;
    for (int sub = 0; sub < nsub; sub++) {
        int base = start + sub*32;
        if (tid < 512) {
            int row = tid >> 4, c4 = tid & 15;
            int gt = base + row;
            float4 v = (gt < end) ? *(const float4*)&g_qkv[(size_t)gt*QKVD + 1024 + h*DH + c4*4]
                                  : make_float4(0,0,0,0);
            *(float4*)&vs[row][c4*4] = v;
        }
        {
            int mm = tid >> 5, tok = tid & 31;
            int gt = base + tok;
            a3s[mm][tok] = (gt < end) ? g_attn3[((size_t)h*MM + mm)*NPAD + gt] : 0.f;
        }
        __syncthreads();
        #pragma unroll
        for (int tok = 0; tok < 32; tok++) {
            float a = a3s[m][tok];
            float2 v = *(const float2*)&vs[tok][lane*2];
            acc.x += a*v.x; acc.y += a*v.y;
        }
        __syncthreads();
    }
    float* dst = g_avp + ((size_t)(ch*HEADS + h)*MM + m)*DH + lane*2;
    dst[0] = acc.x; dst[1] = acc.y;
}

// ---------------- 8b. out_heads = w1 @ av + depthwise conv(v) ---------------
#define OTILE 96
__global__ __launch_bounds__(256)
void outh_kernel(const float* __restrict__ conv_w) {
    int h = blockIdx.y;
    int t0 = blockIdx.x * OTILE;
    int tid = threadIdx.x;
    __shared__ float vtile[OTILE+32][DH];
    __shared__ float w1s[OTILE][MM];
    __shared__ float avs[MM*DH];
    __shared__ float cws[KCONV];
    // v tile with halo
    #pragma unroll
    for (int i = 0; i < (OTILE+32)*16/256; i++) {
        int idx = i*256 + tid;
        int row = idx >> 4, c4 = idx & 15;
        int gt = t0 - 16 + row;
        float4 v = (gt >= 0 && gt < NPAD) ? *(const float4*)&g_qkv[(size_t)gt*QKVD + 1024 + h*DH + c4*4]
                                          : make_float4(0,0,0,0);
        *(float4*)&vtile[row][c4*4] = v;
    }
    for (int idx = tid; idx < OTILE*MM; idx += 256) {
        int r = idx / MM, mm = idx % MM;
        int gt = t0 + r;
        w1s[r][mm] = (gt < NPAD) ? g_w1[((size_t)h*NPAD + gt)*MM + mm] : 0.f;
    }
    for (int idx = tid; idx < MM*DH; idx += 256) {
        float s = 0.f;
        #pragma unroll
        for (int c = 0; c < AVCH; c++) s += g_avp[(size_t)(c*HEADS + h)*MM*DH + idx];
        avs[idx] = s;
    }
    if (tid < KCONV) cws[tid] = conv_w[h*KCONV + tid];
    __syncthreads();
    int d = tid & 63, grp = tid >> 6;   // 4 groups x 24 rows
    for (int rr = 0; rr < OTILE/4; rr++) {
        int r = grp*(OTILE/4) + rr;
        int t = t0 + r;
        if (t >= NPAD) continue;
        float acc = 0.f;
        #pragma unroll
        for (int mm = 0; mm < MM; mm++) acc += w1s[r][mm]*avs[mm*DH + d];
        #pragma unroll
        for (int k = 0; k < KCONV; k++) acc += cws[k]*vtile[r+k][d];
        g_outh[(size_t)t*DIM + h*DH + d] = acc;
    }
}

// ---------------- 11. attn = w1 @ attn3 (537 MB) -----------------------------
__global__ __launch_bounds__(128)
void attn_final_kernel(float* __restrict__ out) {
    int h = blockIdx.z;
    int t0 = blockIdx.y * 32;
    int s = blockIdx.x * 128 + threadIdx.x;
    __shared__ float w1s[32][20];
    for (int idx = threadIdx.x; idx < 32*MM; idx += 128) {
        int r = idx / MM, m = idx % MM;
        int t = t0 + r;
        w1s[r][m] = (t < NPAD) ? g_w1[((size_t)h*NPAD + t)*MM + m] : 0.f;
    }
    float a3[MM];
    if (s < NPAD) {
        #pragma unroll
        for (int m = 0; m < MM; m++) a3[m] = g_attn3[((size_t)h*MM + m)*NPAD + s];
    }
    __syncthreads();
    if (s >= NPAD) return;
    float* base = out + (size_t)h*ATTN_PER_HEAD + (size_t)t0*NPAD + s;
    int rmax = min(32, NPAD - t0);
    for (int r = 0; r < rmax; r++) {
        float4 wa = *(const float4*)&w1s[r][0];
        float4 wb = *(const float4*)&w1s[r][4];
        float4 wc = *(const float4*)&w1s[r][8];
        float4 wd = *(const float4*)&w1s[r][12];
        float w16 = w1s[r][16];
        float acc = wa.x*a3[0] + wa.y*a3[1] + wa.z*a3[2] + wa.w*a3[3]
                  + wb.x*a3[4] + wb.y*a3[5] + wb.z*a3[6] + wb.w*a3[7]
                  + wc.x*a3[8] + wc.y*a3[9] + wc.z*a3[10] + wc.w*a3[11]
                  + wd.x*a3[12]+ wd.y*a3[13]+ wd.z*a3[14]+ wd.w*a3[15]
                  + w16*a3[16];
        base[(size_t)r*NPAD] = acc;
    }
}

// ---------------- launch ----------------------------------------------------
extern "C" void kernel_launch(void* const* d_in, const int* in_sizes, int n_in,
                              void* d_out, int out_size) {
    const float* x      = (const float*)d_in[0];
    const float* norm_w = (const float*)d_in[1];
    const float* norm_b = (const float*)d_in[2];
    const float* w_qkv  = (const float*)d_in[3];
    const float* w_out  = (const float*)d_in[4];
    const float* b_out  = (const float*)d_in[5];
    const float* conv_w = (const float*)d_in[6];
    float* out = (float*)d_out;

    float *p_xp, *p_qkv, *p_outh;
    cudaGetSymbolAddress((void**)&p_xp,   g_xp);
    cudaGetSymbolAddress((void**)&p_qkv,  g_qkv);
    cudaGetSymbolAddress((void**)&p_outh, g_outh);

    ln_kernel<<<NPAD, 256>>>(x, norm_w, norm_b);
    gemm_abT<<<dim3(QKVD/BN, (NPAD+BM-1)/BM), 256>>>(p_xp, w_qkv, p_qkv,
                                                     NPAD, QKVD, DIM, 0, nullptr, nullptr);
    landmark_kernel<<<dim3(MM, 2), 512>>>();
    pinv_kernel<<<HEADS, MM*MM>>>();
    attn1w1_kernel<<<dim3((NPAD+127)/128, HEADS), 128>>>();
    attn3a_kernel<<<dim3((NPAD+127)/128, HEADS), 128>>>();
    attn3b_kernel<<<dim3(MM, HEADS), 256>>>();
    av_kernel<<<dim3(AVCH, HEADS), 544>>>();
    outh_kernel<<<dim3((NPAD+OTILE-1)/OTILE, HEADS), 256>>>(conv_w);
    gemm_abT<<<dim3(DIM/BN, NTOK/BM), 256>>>(p_outh + DIM, w_out, out,
                                             NTOK, DIM, DIM, 1, b_out, x);
    attn_final_kernel<<<dim3((NPAD+127)/128, (NPAD+31)/32, HEADS), 128>>>(out + OUT1_SIZE);
}

// round 5
// speedup vs baseline: 1.7144x; 1.2763x over previous
#include <cuda_runtime.h>
#include <cuda_bf16.h>
#include <math.h>
#include <stdint.h>

#define NTOK 4096
#define NPAD 4097
#define DIM 512
#define HEADS 8
#define DH 64
#define MM 17
#define LBLK 241
#define QKVD 1536
#define KCONV 33
#define OUT1_SIZE (NTOK*DIM)
#define ATTN_PER_HEAD ((size_t)NPAD*NPAD)
#define AVCH 8

// ---------------- scratch ---------------------------------------------------
__device__ float g_qkv[NPAD*QKVD];
__device__ float g_ql[HEADS*MM*DH];
__device__ float g_kl[HEADS*MM*DH];
__device__ float g_attn3[HEADS*MM*NPAD];
__device__ float g_inv[HEADS*MM*MM];
__device__ float g_avp[AVCH*HEADS*MM*DH];
__device__ float g_w1[HEADS*NPAD*MM];
// bf16 3-way splits
__device__ __nv_bfloat16 g_ah[NPAD*DIM], g_am[NPAD*DIM], g_al[NPAD*DIM];
__device__ __nv_bfloat16 g_oh[NPAD*DIM], g_om[NPAD*DIM], g_ol[NPAD*DIM];
__device__ __nv_bfloat16 g_wqh[QKVD*DIM], g_wqm[QKVD*DIM], g_wql[QKVD*DIM];
__device__ __nv_bfloat16 g_woh[DIM*DIM], g_wom[DIM*DIM], g_wol[DIM*DIM];

__device__ __forceinline__ uint32_t s2u(const void* p) {
    return (uint32_t)__cvta_generic_to_shared(p);
}
__device__ __forceinline__ void split3(float x, __nv_bfloat16& h, __nv_bfloat16& m, __nv_bfloat16& l) {
    h = __float2bfloat16(x);
    float r1 = x - __bfloat162float(h);
    m = __float2bfloat16(r1);
    float r2 = r1 - __bfloat162float(m);
    l = __float2bfloat16(r2);
}

// ---------------- 1. LayerNorm -> split bf16 ---------------------------------
__global__ void ln_kernel(const float* __restrict__ x,
                          const float* __restrict__ w,
                          const float* __restrict__ b) {
    int r = blockIdx.x;
    int tid = threadIdx.x;
    if (r == 0) {
        __nv_bfloat16 z = __float2bfloat16(0.f);
        for (int c = tid; c < DIM; c += 256) { g_ah[c]=z; g_am[c]=z; g_al[c]=z; }
        return;
    }
    const float* row = x + (size_t)(r-1)*DIM;
    __shared__ float red[256];
    float s = 0.f;
    for (int c = tid; c < DIM; c += 256) s += row[c];
    red[tid] = s; __syncthreads();
    for (int o = 128; o; o >>= 1) { if (tid < o) red[tid] += red[tid+o]; __syncthreads(); }
    float mu = red[0] * (1.0f/DIM);
    __syncthreads();
    float v = 0.f;
    for (int c = tid; c < DIM; c += 256) { float d = row[c]-mu; v += d*d; }
    red[tid] = v; __syncthreads();
    for (int o = 128; o; o >>= 1) { if (tid < o) red[tid] += red[tid+o]; __syncthreads(); }
    float rs = rsqrtf(red[0]*(1.0f/DIM) + 1e-5f);
    for (int c = tid; c < DIM; c += 256) {
        float val = (row[c]-mu)*rs*w[c] + b[c];
        __nv_bfloat16 h, m, l;
        split3(val, h, m, l);
        size_t idx = (size_t)r*DIM + c;
        g_ah[idx]=h; g_am[idx]=m; g_al[idx]=l;
    }
}

// ---------------- weight split ------------------------------------------------
__global__ void wcvt_kernel(const float* __restrict__ w,
                            __nv_bfloat16* __restrict__ h,
                            __nv_bfloat16* __restrict__ m,
                            __nv_bfloat16* __restrict__ l, int n) {
    int i = blockIdx.x*256 + threadIdx.x;
    if (i < n) split3(w[i], h[i], m[i], l[i]);
}

// ---------------- mma.sync bf16 GEMM: C = A(MxK) @ B^T ------------------------
// 3-way split inputs; 6 combo passes accumulated in fp32 fragments.
// mode 0: scale cols<512 by 0.125. mode 1: + bias + resid.
#define TPAD 40
#define TILE_B (128*TPAD*2)      // 10240 bytes per tile
#define STAGE_B (6*TILE_B)       // 61440
#define GSMEM (2*STAGE_B)        // 122880

__device__ __forceinline__ void cp16(uint32_t daddr, const void* g, int sz) {
    asm volatile("cp.async.ca.shared.global [%0], [%1], 16, %2;"
                 :: "r"(daddr), "l"(g), "r"(sz));
}
__device__ __forceinline__ void ldm4(uint32_t* r, uint32_t addr) {
    asm volatile("ldmatrix.sync.aligned.m8n8.x4.shared.b16 {%0,%1,%2,%3}, [%4];"
                 : "=r"(r[0]), "=r"(r[1]), "=r"(r[2]), "=r"(r[3]) : "r"(addr));
}
__device__ __forceinline__ void mma16816(float* c, const uint32_t* a, const uint32_t* b) {
    asm volatile("mma.sync.aligned.m16n8k16.row.col.f32.bf16.bf16.f32 "
                 "{%0,%1,%2,%3}, {%4,%5,%6,%7}, {%8,%9}, {%0,%1,%2,%3};"
                 : "+f"(c[0]), "+f"(c[1]), "+f"(c[2]), "+f"(c[3])
                 : "r"(a[0]), "r"(a[1]), "r"(a[2]), "r"(a[3]), "r"(b[0]), "r"(b[1]));
}

__global__ __launch_bounds__(256, 1)
void gemm_mma(const __nv_bfloat16* __restrict__ a0, const __nv_bfloat16* __restrict__ a1,
              const __nv_bfloat16* __restrict__ a2,
              const __nv_bfloat16* __restrict__ b0, const __nv_bfloat16* __restrict__ b1,
              const __nv_bfloat16* __restrict__ b2,
              float* __restrict__ C, int M, int N, int K, int mode,
              const float* __restrict__ bias, const float* __restrict__ resid) {
    extern __shared__ char smem[];
    uint32_t sbase = s2u(smem);
    int tid = threadIdx.x, lane = tid & 31, wid = tid >> 5;
    int warp_m = wid & 3, warp_n = wid >> 2;
    int m0 = blockIdx.y * 128, n0 = blockIdx.x * 128;
    const __nv_bfloat16* asrc[3] = {a0, a1, a2};
    const __nv_bfloat16* bsrc[3] = {b0, b1, b2};

    int ldrow = tid >> 2, ldc4 = tid & 3;           // staging: 2 chunks/tile/thread
    float acc[2][8][4];
    #pragma unroll
    for (int i = 0; i < 2; i++)
        #pragma unroll
        for (int j = 0; j < 8; j++)
            #pragma unroll
            for (int v = 0; v < 4; v++) acc[i][j][v] = 0.f;

    int nchunks = K / 32;
    // ---- prologue: stage chunk 0 into buffer 0
    {
        int k0 = 0;
        #pragma unroll
        for (int s = 0; s < 6; s++) {
            const __nv_bfloat16* src = (s < 3) ? asrc[s] : bsrc[s-3];
            int base = (s < 3) ? m0 : n0;
            uint32_t tb = sbase + s*TILE_B;
            #pragma unroll
            for (int i = 0; i < 2; i++) {
                int row = ldrow + i*64;
                int gr = base + row;
                int ok = (s >= 3) || (gr < M);
                int grc = ok ? gr : 0;
                cp16(tb + row*80 + ldc4*16, src + (size_t)grc*K + k0 + ldc4*8, ok ? 16 : 0);
            }
        }
        asm volatile("cp.async.commit_group;");
    }

    const int pa[6] = {0,0,1,1,0,2};
    const int pb[6] = {0,1,0,1,2,0};
    // per-thread ldmatrix offsets (within a tile)
    int arow = warp_m*32 + (lane & 15);
    int akoff = ((lane >> 4) << 3);
    int brow = warp_n*64 + (lane & 7) + ((lane >> 4) << 3);
    int bkoff = ((lane >> 3) & 1) << 3;

    for (int c = 0; c < nchunks; c++) {
        int st = c & 1;
        if (c + 1 < nchunks) {
            int k0 = (c+1) * 32;
            uint32_t stb = sbase + (st^1)*STAGE_B;
            #pragma unroll
            for (int s = 0; s < 6; s++) {
                const __nv_bfloat16* src = (s < 3) ? asrc[s] : bsrc[s-3];
                int base = (s < 3) ? m0 : n0;
                uint32_t tb = stb + s*TILE_B;
                #pragma unroll
                for (int i = 0; i < 2; i++) {
                    int row = ldrow + i*64;
                    int gr = base + row;
                    int ok = (s >= 3) || (gr < M);
                    int grc = ok ? gr : 0;
                    cp16(tb + row*80 + ldc4*16, src + (size_t)grc*K + k0 + ldc4*8, ok ? 16 : 0);
                }
            }
            asm volatile("cp.async.commit_group;");
            asm volatile("cp.async.wait_group 1;");
        } else {
            asm volatile("cp.async.wait_group 0;");
        }
        __syncthreads();
        uint32_t stb = sbase + st*STAGE_B;
        #pragma unroll
        for (int k16 = 0; k16 < 2; k16++) {
            uint32_t afr[3][2][4];
            uint32_t bfr[3][16];
            #pragma unroll
            for (int s = 0; s < 3; s++) {
                #pragma unroll
                for (int mi = 0; mi < 2; mi++)
                    ldm4(afr[s][mi], stb + s*TILE_B + (arow + mi*16)*80 + (akoff + k16*16)*2);
                #pragma unroll
                for (int g = 0; g < 4; g++)
                    ldm4(&bfr[s][g*4], stb + (3+s)*TILE_B + (brow + g*16)*80 + (bkoff + k16*16)*2);
            }
            #pragma unroll
            for (int mi = 0; mi < 2; mi++)
                #pragma unroll
                for (int nj = 0; nj < 8; nj++) {
                    int g4 = (nj >> 1)*4 + (nj & 1)*2;
                    #pragma unroll
                    for (int t = 0; t < 6; t++)
                        mma16816(acc[mi][nj], afr[pa[t]][mi], &bfr[pb[t]][g4]);
                }
        }
        __syncthreads();
    }

    // ---- epilogue
    int g = lane >> 2, tg = lane & 3;
    #pragma unroll
    for (int mi = 0; mi < 2; mi++) {
        #pragma unroll
        for (int nj = 0; nj < 8; nj++) {
            int col = n0 + warp_n*64 + nj*8 + tg*2;
            int r0 = m0 + warp_m*32 + mi*16 + g;
            int r1 = r0 + 8;
            float v0 = acc[mi][nj][0], v1 = acc[mi][nj][1];
            float v2 = acc[mi][nj][2], v3 = acc[mi][nj][3];
            if (mode == 0) {
                if (col < 512) { v0 *= 0.125f; v1 *= 0.125f; v2 *= 0.125f; v3 *= 0.125f; }
                if (r0 < M) { C[(size_t)r0*N + col] = v0; C[(size_t)r0*N + col + 1] = v1; }
                if (r1 < M) { C[(size_t)r1*N + col] = v2; C[(size_t)r1*N + col + 1] = v3; }
            } else {
                float bb0 = bias[col], bb1 = bias[col+1];
                if (r0 < M) {
                    size_t o = (size_t)r0*N + col;
                    C[o]   = v0 + bb0 + resid[o];
                    C[o+1] = v1 + bb1 + resid[o+1];
                }
                if (r1 < M) {
                    size_t o = (size_t)r1*N + col;
                    C[o]   = v2 + bb0 + resid[o];
                    C[o+1] = v3 + bb1 + resid[o+1];
                }
            }
        }
    }
}

// ---------------- 3. landmarks ------------------------------------------------
__global__ void landmark_kernel() {
    int m = blockIdx.x, which = blockIdx.y;
    int c = threadIdx.x;
    int base = which ? 512 : 0;
    const float* p = g_qkv + (size_t)(m*LBLK)*QKVD + base + c;
    float s = 0.f;
    for (int i = 0; i < LBLK; i++) s += p[(size_t)i*QKVD];
    float v = s * (1.0f/LBLK);
    int h = c >> 6, d = c & 63;
    if (which) g_kl[(h*MM+m)*DH + d] = v; else g_ql[(h*MM+m)*DH + d] = v;
}

// ---------------- 5. attn2 softmax + pinv --------------------------------------
__global__ void pinv_kernel() {
    int h = blockIdx.x;
    int tid = threadIdx.x;          // 289
    int i = tid / MM, j = tid % MM;
    __shared__ float a[MM][MM], zz[2][MM][MM], az[MM][MM], t2[MM][MM], t3[MM][MM];
    __shared__ float sc;
    {
        const float* ql = g_ql + (h*MM + i)*DH;
        const float* kl = g_kl + (h*MM + j)*DH;
        float s = 0.f;
        #pragma unroll
        for (int d = 0; d < DH; d++) s += ql[d]*kl[d];
        a[i][j] = s;
    }
    __syncthreads();
    if (tid < MM) {
        float mx = -INFINITY;
        for (int c = 0; c < MM; c++) mx = fmaxf(mx, a[tid][c]);
        float s = 0.f;
        for (int c = 0; c < MM; c++) { float e = expf(a[tid][c]-mx); a[tid][c] = e; s += e; }
        float inv = 1.f/s;
        for (int c = 0; c < MM; c++) a[tid][c] *= inv;
    }
    __syncthreads();
    if (tid == 0) {
        float col = 0.f, row = 0.f;
        for (int r = 0; r < MM; r++) { float s = 0.f; for (int c = 0; c < MM; c++) s += fabsf(a[r][c]); col = fmaxf(col, s); }
        for (int c = 0; c < MM; c++) { float s = 0.f; for (int r = 0; r < MM; r++) s += fabsf(a[r][c]); row = fmaxf(row, s); }
        sc = 1.f/(col*row);
    }
    __syncthreads();
    int zc = 0;
    zz[0][i][j] = a[j][i] * sc;
    __syncthreads();
    for (int it = 0; it < 6; it++) {
        float s = 0.f;
        for (int k = 0; k < MM; k++) s += a[i][k]*zz[zc][k][j];
        az[i][j] = s; __syncthreads();
        s = 0.f;
        for (int k = 0; k < MM; k++) s += az[i][k]*((k==j ? 7.f : 0.f) - az[k][j]);
        t2[i][j] = (i==j ? 15.f : 0.f) - s; __syncthreads();
        s = 0.f;
        for (int k = 0; k < MM; k++) s += az[i][k]*t2[k][j];
        t3[i][j] = (i==j ? 13.f : 0.f) - s; __syncthreads();
        s = 0.f;
        for (int k = 0; k < MM; k++) s += zz[zc][i][k]*t3[k][j];
        zz[1-zc][i][j] = 0.25f*s; zc ^= 1; __syncthreads();
    }
    g_inv[(h*MM + i)*MM + j] = zz[zc][i][j];
}

// ---------------- 4+8a fused: w1 = softmax(q @ kl^T) @ inv ----------------------
#define QS 68
__global__ __launch_bounds__(128)
void attn1w1_kernel() {
    int h = blockIdx.y;
    int t0 = blockIdx.x * 128;
    int tid = threadIdx.x;
    __shared__ float qs[128][QS];
    __shared__ float kls[MM*DH];
    __shared__ float invs[MM*MM];
    #pragma unroll
    for (int i = 0; i < 16; i++) {
        int idx = i*128 + tid;
        int row = idx >> 4, c4 = idx & 15;
        int gt = t0 + row;
        float4 v = (gt < NPAD) ? *(const float4*)&g_qkv[(size_t)gt*QKVD + h*DH + c4*4]
                               : make_float4(0,0,0,0);
        *(float4*)&qs[row][c4*4] = v;
    }
    for (int idx = tid; idx < MM*DH; idx += 128) kls[idx] = g_kl[h*MM*DH + idx];
    for (int idx = tid; idx < MM*MM; idx += 128) invs[idx] = g_inv[h*MM*MM + idx];
    __syncthreads();
    int t = t0 + tid;
    if (t >= NPAD) return;
    float lg[MM];
    #pragma unroll
    for (int m = 0; m < MM; m++) lg[m] = 0.f;
    #pragma unroll
    for (int d4 = 0; d4 < 16; d4++) {
        float4 q4 = *(const float4*)&qs[tid][d4*4];
        #pragma unroll
        for (int m = 0; m < MM; m++) {
            float4 k4 = *(const float4*)&kls[m*DH + d4*4];
            lg[m] += q4.x*k4.x + q4.y*k4.y + q4.z*k4.z + q4.w*k4.w;
        }
    }
    float mx = lg[0];
    #pragma unroll
    for (int m = 1; m < MM; m++) mx = fmaxf(mx, lg[m]);
    float sum = 0.f;
    #pragma unroll
    for (int m = 0; m < MM; m++) { lg[m] = expf(lg[m]-mx); sum += lg[m]; }
    float inv = 1.f/sum;
    #pragma unroll
    for (int m = 0; m < MM; m++) lg[m] *= inv;
    float* wout = g_w1 + ((size_t)h*NPAD + t)*MM;
    #pragma unroll
    for (int j = 0; j < MM; j++) {
        float s = 0.f;
        #pragma unroll
        for (int k = 0; k < MM; k++) s += lg[k]*invs[k*MM + j];
        wout[j] = s;
    }
}

// ---------------- 6a. attn3 logits ----------------------------------------------
__global__ __launch_bounds__(128)
void attn3a_kernel() {
    int h = blockIdx.y;
    int t0 = blockIdx.x * 128;
    int tid = threadIdx.x;
    __shared__ float ks[128][QS];
    __shared__ float qls[MM*DH];
    #pragma unroll
    for (int i = 0; i < 16; i++) {
        int idx = i*128 + tid;
        int row = idx >> 4, c4 = idx & 15;
        int gt = t0 + row;
        float4 v = (gt < NPAD) ? *(const float4*)&g_qkv[(size_t)gt*QKVD + 512 + h*DH + c4*4]
                               : make_float4(0,0,0,0);
        *(float4*)&ks[row][c4*4] = v;
    }
    for (int idx = tid; idx < MM*DH; idx += 128) qls[idx] = g_ql[h*MM*DH + idx];
    __syncthreads();
    int t = t0 + tid;
    if (t >= NPAD) return;
    float lg[MM];
    #pragma unroll
    for (int m = 0; m < MM; m++) lg[m] = 0.f;
    #pragma unroll
    for (int d4 = 0; d4 < 16; d4++) {
        float4 k4 = *(const float4*)&ks[tid][d4*4];
        #pragma unroll
        for (int m = 0; m < MM; m++) {
            float4 q4 = *(const float4*)&qls[m*DH + d4*4];
            lg[m] += q4.x*k4.x + q4.y*k4.y + q4.z*k4.z + q4.w*k4.w;
        }
    }
    #pragma unroll
    for (int m = 0; m < MM; m++)
        g_attn3[((size_t)h*MM + m)*NPAD + t] = lg[m];
}

// ---------------- 6b. attn3 softmax normalize ------------------------------------
__global__ void attn3b_kernel() {
    int m = blockIdx.x, h = blockIdx.y;
    int tid = threadIdx.x;
    __shared__ float buf[NPAD];
    __shared__ float red[256];
    float* rowp = g_attn3 + ((size_t)h*MM + m)*NPAD;
    float lmax = -INFINITY;
    for (int t = tid; t < NPAD; t += 256) { float v = rowp[t]; buf[t] = v; lmax = fmaxf(lmax, v); }
    red[tid] = lmax; __syncthreads();
    for (int o = 128; o; o >>= 1) { if (tid < o) red[tid] = fmaxf(red[tid], red[tid+o]); __syncthreads(); }
    float mx = red[0];
    __syncthreads();
    float lsum = 0.f;
    for (int t = tid; t < NPAD; t += 256) { float e = expf(buf[t]-mx); buf[t] = e; lsum += e; }
    red[tid] = lsum; __syncthreads();
    for (int o = 128; o; o >>= 1) { if (tid < o) red[tid] += red[tid+o]; __syncthreads(); }
    float inv = 1.f / red[0];
    for (int t = tid; t < NPAD; t += 256) rowp[t] = buf[t]*inv;
}

// ---------------- 7. av partials ---------------------------------------------------
__global__ __launch_bounds__(544)
void av_kernel() {
    int ch = blockIdx.x, h = blockIdx.y;
    int tid = threadIdx.x;
    int m = tid >> 5, lane = tid & 31;
    int start = ch * 512;
    int end = min(start + 512, NPAD);
    __shared__ float vs[32][QS];
    __shared__ float a3s[MM][32];
    float2 acc = make_float2(0.f, 0.f);
    int nsub = (end - start + 31) >> 5;
    for (int sub = 0; sub < nsub; sub++) {
        int base = start + sub*32;
        if (tid < 512) {
            int row = tid >> 4, c4 = tid & 15;
            int gt = base + row;
            float4 v = (gt < end) ? *(const float4*)&g_qkv[(size_t)gt*QKVD + 1024 + h*DH + c4*4]
                                  : make_float4(0,0,0,0);
            *(float4*)&vs[row][c4*4] = v;
        }
        {
            int mm = tid >> 5, tok = tid & 31;
            int gt = base + tok;
            a3s[mm][tok] = (gt < end) ? g_attn3[((size_t)h*MM + mm)*NPAD + gt] : 0.f;
        }
        __syncthreads();
        #pragma unroll
        for (int tok = 0; tok < 32; tok++) {
            float a = a3s[m][tok];
            float2 v = *(const float2*)&vs[tok][lane*2];
            acc.x += a*v.x; acc.y += a*v.y;
        }
        __syncthreads();
    }
    float* dst = g_avp + ((size_t)(ch*HEADS + h)*MM + m)*DH + lane*2;
    dst[0] = acc.x; dst[1] = acc.y;
}

// ---------------- 8b. out_heads = w1 @ av + conv -> split bf16 ---------------------
#define OTILE 96
__global__ __launch_bounds__(256)
void outh_kernel(const float* __restrict__ conv_w) {
    int h = blockIdx.y;
    int t0 = blockIdx.x * OTILE;
    int tid = threadIdx.x;
    __shared__ float vtile[OTILE+32][DH];
    __shared__ float w1s[OTILE][MM];
    __shared__ float avs[MM*DH];
    __shared__ float cws[KCONV];
    #pragma unroll
    for (int i = 0; i < (OTILE+32)*16/256; i++) {
        int idx = i*256 + tid;
        int row = idx >> 4, c4 = idx & 15;
        int gt = t0 - 16 + row;
        float4 v = (gt >= 0 && gt < NPAD) ? *(const float4*)&g_qkv[(size_t)gt*QKVD + 1024 + h*DH + c4*4]
                                          : make_float4(0,0,0,0);
        *(float4*)&vtile[row][c4*4] = v;
    }
    for (int idx = tid; idx < OTILE*MM; idx += 256) {
        int r = idx / MM, mm = idx % MM;
        int gt = t0 + r;
        w1s[r][mm] = (gt < NPAD) ? g_w1[((size_t)h*NPAD + gt)*MM + mm] : 0.f;
    }
    for (int idx = tid; idx < MM*DH; idx += 256) {
        float s = 0.f;
        #pragma unroll
        for (int c = 0; c < AVCH; c++) s += g_avp[(size_t)(c*HEADS + h)*MM*DH + idx];
        avs[idx] = s;
    }
    if (tid < KCONV) cws[tid] = conv_w[h*KCONV + tid];
    __syncthreads();
    int d = tid & 63, grp = tid >> 6;
    for (int rr = 0; rr < OTILE/4; rr++) {
        int r = grp*(OTILE/4) + rr;
        int t = t0 + r;
        if (t >= NPAD) continue;
        float acc = 0.f;
        #pragma unroll
        for (int mm = 0; mm < MM; mm++) acc += w1s[r][mm]*avs[mm*DH + d];
        #pragma unroll
        for (int k = 0; k < KCONV; k++) acc += cws[k]*vtile[r+k][d];
        size_t idx = (size_t)t*DIM + h*DH + d;
        __nv_bfloat16 bh, bm, bl;
        split3(acc, bh, bm, bl);
        g_oh[idx]=bh; g_om[idx]=bm; g_ol[idx]=bl;
    }
}

// ---------------- 11. attn = w1 @ attn3 (537 MB) ------------------------------------
__global__ __launch_bounds__(128)
void attn_final_kernel(float* __restrict__ out) {
    int h = blockIdx.z;
    int t0 = blockIdx.y * 32;
    int s = blockIdx.x * 128 + threadIdx.x;
    __shared__ float w1s[32][20];
    for (int idx = threadIdx.x; idx < 32*MM; idx += 128) {
        int r = idx / MM, m = idx % MM;
        int t = t0 + r;
        w1s[r][m] = (t < NPAD) ? g_w1[((size_t)h*NPAD + t)*MM + m] : 0.f;
    }
    float a3[MM];
    if (s < NPAD) {
        #pragma unroll
        for (int m = 0; m < MM; m++) a3[m] = g_attn3[((size_t)h*MM + m)*NPAD + s];
    }
    __syncthreads();
    if (s >= NPAD) return;
    float* base = out + (size_t)h*ATTN_PER_HEAD + (size_t)t0*NPAD + s;
    int rmax = min(32, NPAD - t0);
    for (int r = 0; r < rmax; r++) {
        float4 wa = *(const float4*)&w1s[r][0];
        float4 wb = *(const float4*)&w1s[r][4];
        float4 wc = *(const float4*)&w1s[r][8];
        float4 wd = *(const float4*)&w1s[r][12];
        float w16 = w1s[r][16];
        float acc = wa.x*a3[0] + wa.y*a3[1] + wa.z*a3[2] + wa.w*a3[3]
                  + wb.x*a3[4] + wb.y*a3[5] + wb.z*a3[6] + wb.w*a3[7]
                  + wc.x*a3[8] + wc.y*a3[9] + wc.z*a3[10] + wc.w*a3[11]
                  + wd.x*a3[12]+ wd.y*a3[13]+ wd.z*a3[14]+ wd.w*a3[15]
                  + w16*a3[16];
        base[(size_t)r*NPAD] = acc;
    }
}

// ---------------- launch -------------------------------------------------------------
extern "C" void kernel_launch(void* const* d_in, const int* in_sizes, int n_in,
                              void* d_out, int out_size) {
    const float* x      = (const float*)d_in[0];
    const float* norm_w = (const float*)d_in[1];
    const float* norm_b = (const float*)d_in[2];
    const float* w_qkv  = (const float*)d_in[3];
    const float* w_out  = (const float*)d_in[4];
    const float* b_out  = (const float*)d_in[5];
    const float* conv_w = (const float*)d_in[6];
    float* out = (float*)d_out;

    float* p_qkv;
    cudaGetSymbolAddress((void**)&p_qkv, g_qkv);
    __nv_bfloat16 *p_ah, *p_am, *p_al, *p_oh, *p_om, *p_ol;
    __nv_bfloat16 *p_wqh, *p_wqm, *p_wql, *p_woh, *p_wom, *p_wol;
    cudaGetSymbolAddress((void**)&p_ah, g_ah);  cudaGetSymbolAddress((void**)&p_am, g_am);
    cudaGetSymbolAddress((void**)&p_al, g_al);  cudaGetSymbolAddress((void**)&p_oh, g_oh);
    cudaGetSymbolAddress((void**)&p_om, g_om);  cudaGetSymbolAddress((void**)&p_ol, g_ol);
    cudaGetSymbolAddress((void**)&p_wqh, g_wqh); cudaGetSymbolAddress((void**)&p_wqm, g_wqm);
    cudaGetSymbolAddress((void**)&p_wql, g_wql); cudaGetSymbolAddress((void**)&p_woh, g_woh);
    cudaGetSymbolAddress((void**)&p_wom, g_wom); cudaGetSymbolAddress((void**)&p_wol, g_wol);

    cudaFuncSetAttribute(gemm_mma, cudaFuncAttributeMaxDynamicSharedMemorySize, GSMEM);

    ln_kernel<<<NPAD, 256>>>(x, norm_w, norm_b);
    wcvt_kernel<<<(QKVD*DIM + 255)/256, 256>>>(w_qkv, p_wqh, p_wqm, p_wql, QKVD*DIM);
    wcvt_kernel<<<(DIM*DIM + 255)/256, 256>>>(w_out, p_woh, p_wom, p_wol, DIM*DIM);
    // QKV: [4097,1536] = A[4097,512] @ Wqkv^T (q scaled in epilogue)
    gemm_mma<<<dim3(QKVD/128, (NPAD+127)/128), 256, GSMEM>>>(
        p_ah, p_am, p_al, p_wqh, p_wqm, p_wql, p_qkv, NPAD, QKVD, DIM, 0, nullptr, nullptr);
    landmark_kernel<<<dim3(MM, 2), 512>>>();
    pinv_kernel<<<HEADS, MM*MM>>>();
    attn1w1_kernel<<<dim3((NPAD+127)/128, HEADS), 128>>>();
    attn3a_kernel<<<dim3((NPAD+127)/128, HEADS), 128>>>();
    attn3b_kernel<<<dim3(MM, HEADS), 256>>>();
    av_kernel<<<dim3(AVCH, HEADS), 544>>>();
    outh_kernel<<<dim3((NPAD+OTILE-1)/OTILE, HEADS), 256>>>(conv_w);
    // out-proj: rows 1..4096 of out-heads (skip pad row 0)
    gemm_mma<<<dim3(DIM/128, NTOK/128), 256, GSMEM>>>(
        p_oh + DIM, p_om + DIM, p_ol + DIM, p_woh, p_wom, p_wol,
        out, NTOK, DIM, DIM, 1, b_out, x);
    attn_final_kernel<<<dim3((NPAD+127)/128, (NPAD+31)/32, HEADS), 128>>>(out + OUT1_SIZE);
}

// round 6
// speedup vs baseline: 2.0676x; 1.2060x over previous
#include <cuda_runtime.h>
#include <cuda_bf16.h>
#include <math.h>
#include <stdint.h>

#define NTOK 4096
#define NPAD 4097
#define DIM 512
#define HEADS 8
#define DH 64
#define MM 17
#define LBLK 241
#define QKVD 1536
#define KCONV 33
#define OUT1_SIZE (NTOK*DIM)
#define ATTN_PER_HEAD ((size_t)NPAD*NPAD)
#define AVCH 8

// ---------------- scratch ---------------------------------------------------
__device__ float g_qkv[NPAD*QKVD];
__device__ float g_ql[HEADS*MM*DH];
__device__ float g_kl[HEADS*MM*DH];
__device__ float g_attn3[HEADS*MM*NPAD];
__device__ float g_inv[HEADS*MM*MM];
__device__ float g_avp[AVCH*HEADS*MM*DH];
__device__ float g_w1[HEADS*NPAD*MM];
// bf16 2-way splits (hi, mid)
__device__ __nv_bfloat16 g_ah[NPAD*DIM], g_am[NPAD*DIM];
__device__ __nv_bfloat16 g_oh[NPAD*DIM], g_om[NPAD*DIM];
__device__ __nv_bfloat16 g_wqh[QKVD*DIM], g_wqm[QKVD*DIM];
__device__ __nv_bfloat16 g_woh[DIM*DIM], g_wom[DIM*DIM];

__device__ __forceinline__ uint32_t s2u(const void* p) {
    return (uint32_t)__cvta_generic_to_shared(p);
}
__device__ __forceinline__ void split2(float x, __nv_bfloat16& h, __nv_bfloat16& m) {
    h = __float2bfloat16(x);
    float r1 = x - __bfloat162float(h);
    m = __float2bfloat16(r1);
}

// ---------------- 1. LayerNorm -> split bf16 ---------------------------------
__global__ void ln_kernel(const float* __restrict__ x,
                          const float* __restrict__ w,
                          const float* __restrict__ b) {
    int r = blockIdx.x;
    int tid = threadIdx.x;
    if (r == 0) {
        __nv_bfloat16 z = __float2bfloat16(0.f);
        for (int c = tid; c < DIM; c += 256) { g_ah[c]=z; g_am[c]=z; }
        return;
    }
    const float* row = x + (size_t)(r-1)*DIM;
    __shared__ float red[256];
    float s = 0.f;
    for (int c = tid; c < DIM; c += 256) s += row[c];
    red[tid] = s; __syncthreads();
    for (int o = 128; o; o >>= 1) { if (tid < o) red[tid] += red[tid+o]; __syncthreads(); }
    float mu = red[0] * (1.0f/DIM);
    __syncthreads();
    float v = 0.f;
    for (int c = tid; c < DIM; c += 256) { float d = row[c]-mu; v += d*d; }
    red[tid] = v; __syncthreads();
    for (int o = 128; o; o >>= 1) { if (tid < o) red[tid] += red[tid+o]; __syncthreads(); }
    float rs = rsqrtf(red[0]*(1.0f/DIM) + 1e-5f);
    for (int c = tid; c < DIM; c += 256) {
        float val = (row[c]-mu)*rs*w[c] + b[c];
        __nv_bfloat16 h, m;
        split2(val, h, m);
        size_t idx = (size_t)r*DIM + c;
        g_ah[idx]=h; g_am[idx]=m;
    }
}

// ---------------- weight split ------------------------------------------------
__global__ void wcvt_kernel(const float* __restrict__ w,
                            __nv_bfloat16* __restrict__ h,
                            __nv_bfloat16* __restrict__ m, int n) {
    int i = blockIdx.x*256 + threadIdx.x;
    if (i < n) split2(w[i], h[i], m[i]);
}

// ---------------- mma.sync bf16 GEMM: C = A(MxK) @ B^T ------------------------
// 2-way split inputs; 3 combo passes (hh, hm, mh) accumulated in fp32.
// mode 0: scale cols<512 by 0.125. mode 1: + bias + resid.
#define TPAD 40
#define TILE_B (128*TPAD*2)      // 10240 bytes per tile
#define STAGE_B (4*TILE_B)       // 40960
#define GSMEM (3*STAGE_B)        // 122880 (3 stages)

__device__ __forceinline__ void cp16(uint32_t daddr, const void* g, int sz) {
    asm volatile("cp.async.ca.shared.global [%0], [%1], 16, %2;"
                 :: "r"(daddr), "l"(g), "r"(sz));
}
__device__ __forceinline__ void ldm4(uint32_t* r, uint32_t addr) {
    asm volatile("ldmatrix.sync.aligned.m8n8.x4.shared.b16 {%0,%1,%2,%3}, [%4];"
                 : "=r"(r[0]), "=r"(r[1]), "=r"(r[2]), "=r"(r[3]) : "r"(addr));
}
__device__ __forceinline__ void mma16816(float* c, const uint32_t* a, const uint32_t* b) {
    asm volatile("mma.sync.aligned.m16n8k16.row.col.f32.bf16.bf16.f32 "
                 "{%0,%1,%2,%3}, {%4,%5,%6,%7}, {%8,%9}, {%0,%1,%2,%3};"
                 : "+f"(c[0]), "+f"(c[1]), "+f"(c[2]), "+f"(c[3])
                 : "r"(a[0]), "r"(a[1]), "r"(a[2]), "r"(a[3]), "r"(b[0]), "r"(b[1]));
}

__global__ __launch_bounds__(256, 1)
void gemm_mma(const __nv_bfloat16* __restrict__ a0, const __nv_bfloat16* __restrict__ a1,
              const __nv_bfloat16* __restrict__ b0, const __nv_bfloat16* __restrict__ b1,
              float* __restrict__ C, int M, int N, int K, int mode,
              const float* __restrict__ bias, const float* __restrict__ resid) {
    extern __shared__ char smem[];
    uint32_t sbase = s2u(smem);
    int tid = threadIdx.x, lane = tid & 31, wid = tid >> 5;
    int warp_m = wid & 3, warp_n = wid >> 2;
    int m0 = blockIdx.y * 128, n0 = blockIdx.x * 128;
    const __nv_bfloat16* asrc[2] = {a0, a1};
    const __nv_bfloat16* bsrc[2] = {b0, b1};

    int ldrow = tid >> 2, ldc4 = tid & 3;
    float acc[2][8][4];
    #pragma unroll
    for (int i = 0; i < 2; i++)
        #pragma unroll
        for (int j = 0; j < 8; j++)
            #pragma unroll
            for (int v = 0; v < 4; v++) acc[i][j][v] = 0.f;

    int nchunks = K / 32;

    // stage one chunk into stage buffer `buf`
    auto stage = [&](int chunk, int buf) {
        int k0 = chunk * 32;
        uint32_t stb = sbase + buf*STAGE_B;
        #pragma unroll
        for (int s = 0; s < 4; s++) {
            const __nv_bfloat16* src = (s < 2) ? asrc[s] : bsrc[s-2];
            int base = (s < 2) ? m0 : n0;
            uint32_t tb = stb + s*TILE_B;
            #pragma unroll
            for (int i = 0; i < 2; i++) {
                int row = ldrow + i*64;
                int gr = base + row;
                int ok = (s >= 2) || (gr < M);
                int grc = ok ? gr : 0;
                cp16(tb + row*80 + ldc4*16, src + (size_t)grc*K + k0 + ldc4*8, ok ? 16 : 0);
            }
        }
        asm volatile("cp.async.commit_group;");
    };

    stage(0, 0);
    if (nchunks > 1) stage(1, 1);

    // per-thread ldmatrix offsets
    int arow = warp_m*32 + (lane & 15);
    int akoff = ((lane >> 4) << 3);
    int brow = warp_n*64 + (lane & 7) + ((lane >> 4) << 3);
    int bkoff = ((lane >> 3) & 1) << 3;

    for (int c = 0; c < nchunks; c++) {
        if (c + 2 < nchunks) {
            stage(c + 2, (c + 2) % 3);
            asm volatile("cp.async.wait_group 2;");
        } else if (c + 1 < nchunks) {
            asm volatile("cp.async.wait_group 1;");
        } else {
            asm volatile("cp.async.wait_group 0;");
        }
        __syncthreads();
        uint32_t stb = sbase + (c % 3)*STAGE_B;
        #pragma unroll
        for (int k16 = 0; k16 < 2; k16++) {
            uint32_t afr[2][2][4];
            uint32_t bfr[2][16];
            #pragma unroll
            for (int s = 0; s < 2; s++) {
                #pragma unroll
                for (int mi = 0; mi < 2; mi++)
                    ldm4(afr[s][mi], stb + s*TILE_B + (arow + mi*16)*80 + (akoff + k16*16)*2);
                #pragma unroll
                for (int g = 0; g < 4; g++)
                    ldm4(&bfr[s][g*4], stb + (2+s)*TILE_B + (brow + g*16)*80 + (bkoff + k16*16)*2);
            }
            #pragma unroll
            for (int mi = 0; mi < 2; mi++)
                #pragma unroll
                for (int nj = 0; nj < 8; nj++) {
                    int g4 = (nj >> 1)*4 + (nj & 1)*2;
                    mma16816(acc[mi][nj], afr[0][mi], &bfr[0][g4]);   // hh
                    mma16816(acc[mi][nj], afr[0][mi], &bfr[1][g4]);   // hm
                    mma16816(acc[mi][nj], afr[1][mi], &bfr[0][g4]);   // mh
                }
        }
        __syncthreads();
    }

    // ---- epilogue
    int g = lane >> 2, tg = lane & 3;
    #pragma unroll
    for (int mi = 0; mi < 2; mi++) {
        #pragma unroll
        for (int nj = 0; nj < 8; nj++) {
            int col = n0 + warp_n*64 + nj*8 + tg*2;
            int r0 = m0 + warp_m*32 + mi*16 + g;
            int r1 = r0 + 8;
            float v0 = acc[mi][nj][0], v1 = acc[mi][nj][1];
            float v2 = acc[mi][nj][2], v3 = acc[mi][nj][3];
            if (mode == 0) {
                if (col < 512) { v0 *= 0.125f; v1 *= 0.125f; v2 *= 0.125f; v3 *= 0.125f; }
                if (r0 < M) { C[(size_t)r0*N + col] = v0; C[(size_t)r0*N + col + 1] = v1; }
                if (r1 < M) { C[(size_t)r1*N + col] = v2; C[(size_t)r1*N + col + 1] = v3; }
            } else {
                float bb0 = bias[col], bb1 = bias[col+1];
                if (r0 < M) {
                    size_t o = (size_t)r0*N + col;
                    C[o]   = v0 + bb0 + resid[o];
                    C[o+1] = v1 + bb1 + resid[o+1];
                }
                if (r1 < M) {
                    size_t o = (size_t)r1*N + col;
                    C[o]   = v2 + bb0 + resid[o];
                    C[o+1] = v3 + bb1 + resid[o+1];
                }
            }
        }
    }
}

// ---------------- 3. landmarks ------------------------------------------------
__global__ void landmark_kernel() {
    int m = blockIdx.x, which = blockIdx.y;
    int c = threadIdx.x;
    int base = which ? 512 : 0;
    const float* p = g_qkv + (size_t)(m*LBLK)*QKVD + base + c;
    float s = 0.f;
    for (int i = 0; i < LBLK; i++) s += p[(size_t)i*QKVD];
    float v = s * (1.0f/LBLK);
    int h = c >> 6, d = c & 63;
    if (which) g_kl[(h*MM+m)*DH + d] = v; else g_ql[(h*MM+m)*DH + d] = v;
}

// ---------------- 5. attn2 softmax + pinv --------------------------------------
__global__ void pinv_kernel() {
    int h = blockIdx.x;
    int tid = threadIdx.x;          // 289
    int i = tid / MM, j = tid % MM;
    __shared__ float a[MM][MM], zz[2][MM][MM], az[MM][MM], t2[MM][MM], t3[MM][MM];
    __shared__ float sc;
    {
        const float* ql = g_ql + (h*MM + i)*DH;
        const float* kl = g_kl + (h*MM + j)*DH;
        float s = 0.f;
        #pragma unroll
        for (int d = 0; d < DH; d++) s += ql[d]*kl[d];
        a[i][j] = s;
    }
    __syncthreads();
    if (tid < MM) {
        float mx = -INFINITY;
        for (int c = 0; c < MM; c++) mx = fmaxf(mx, a[tid][c]);
        float s = 0.f;
        for (int c = 0; c < MM; c++) { float e = expf(a[tid][c]-mx); a[tid][c] = e; s += e; }
        float inv = 1.f/s;
        for (int c = 0; c < MM; c++) a[tid][c] *= inv;
    }
    __syncthreads();
    if (tid == 0) {
        float col = 0.f, row = 0.f;
        for (int r = 0; r < MM; r++) { float s = 0.f; for (int c = 0; c < MM; c++) s += fabsf(a[r][c]); col = fmaxf(col, s); }
        for (int c = 0; c < MM; c++) { float s = 0.f; for (int r = 0; r < MM; r++) s += fabsf(a[r][c]); row = fmaxf(row, s); }
        sc = 1.f/(col*row);
    }
    __syncthreads();
    int zc = 0;
    zz[0][i][j] = a[j][i] * sc;
    __syncthreads();
    for (int it = 0; it < 6; it++) {
        float s = 0.f;
        for (int k = 0; k < MM; k++) s += a[i][k]*zz[zc][k][j];
        az[i][j] = s; __syncthreads();
        s = 0.f;
        for (int k = 0; k < MM; k++) s += az[i][k]*((k==j ? 7.f : 0.f) - az[k][j]);
        t2[i][j] = (i==j ? 15.f : 0.f) - s; __syncthreads();
        s = 0.f;
        for (int k = 0; k < MM; k++) s += az[i][k]*t2[k][j];
        t3[i][j] = (i==j ? 13.f : 0.f) - s; __syncthreads();
        s = 0.f;
        for (int k = 0; k < MM; k++) s += zz[zc][i][k]*t3[k][j];
        zz[1-zc][i][j] = 0.25f*s; zc ^= 1; __syncthreads();
    }
    g_inv[(h*MM + i)*MM + j] = zz[zc][i][j];
}

// ---------------- 4+8a fused: w1 = softmax(q @ kl^T) @ inv ----------------------
#define QS 68
__global__ __launch_bounds__(128)
void attn1w1_kernel() {
    int h = blockIdx.y;
    int t0 = blockIdx.x * 128;
    int tid = threadIdx.x;
    __shared__ float qs[128][QS];
    __shared__ float kls[MM*DH];
    __shared__ float invs[MM*MM];
    #pragma unroll
    for (int i = 0; i < 16; i++) {
        int idx = i*128 + tid;
        int row = idx >> 4, c4 = idx & 15;
        int gt = t0 + row;
        float4 v = (gt < NPAD) ? *(const float4*)&g_qkv[(size_t)gt*QKVD + h*DH + c4*4]
                               : make_float4(0,0,0,0);
        *(float4*)&qs[row][c4*4] = v;
    }
    for (int idx = tid; idx < MM*DH; idx += 128) kls[idx] = g_kl[h*MM*DH + idx];
    for (int idx = tid; idx < MM*MM; idx += 128) invs[idx] = g_inv[h*MM*MM + idx];
    __syncthreads();
    int t = t0 + tid;
    if (t >= NPAD) return;
    float lg[MM];
    #pragma unroll
    for (int m = 0; m < MM; m++) lg[m] = 0.f;
    #pragma unroll
    for (int d4 = 0; d4 < 16; d4++) {
        float4 q4 = *(const float4*)&qs[tid][d4*4];
        #pragma unroll
        for (int m = 0; m < MM; m++) {
            float4 k4 = *(const float4*)&kls[m*DH + d4*4];
            lg[m] += q4.x*k4.x + q4.y*k4.y + q4.z*k4.z + q4.w*k4.w;
        }
    }
    float mx = lg[0];
    #pragma unroll
    for (int m = 1; m < MM; m++) mx = fmaxf(mx, lg[m]);
    float sum = 0.f;
    #pragma unroll
    for (int m = 0; m < MM; m++) { lg[m] = expf(lg[m]-mx); sum += lg[m]; }
    float inv = 1.f/sum;
    #pragma unroll
    for (int m = 0; m < MM; m++) lg[m] *= inv;
    float* wout = g_w1 + ((size_t)h*NPAD + t)*MM;
    #pragma unroll
    for (int j = 0; j < MM; j++) {
        float s = 0.f;
        #pragma unroll
        for (int k = 0; k < MM; k++) s += lg[k]*invs[k*MM + j];
        wout[j] = s;
    }
}

// ---------------- 6a. attn3 logits ----------------------------------------------
__global__ __launch_bounds__(128)
void attn3a_kernel() {
    int h = blockIdx.y;
    int t0 = blockIdx.x * 128;
    int tid = threadIdx.x;
    __shared__ float ks[128][QS];
    __shared__ float qls[MM*DH];
    #pragma unroll
    for (int i = 0; i < 16; i++) {
        int idx = i*128 + tid;
        int row = idx >> 4, c4 = idx & 15;
        int gt = t0 + row;
        float4 v = (gt < NPAD) ? *(const float4*)&g_qkv[(size_t)gt*QKVD + 512 + h*DH + c4*4]
                               : make_float4(0,0,0,0);
        *(float4*)&ks[row][c4*4] = v;
    }
    for (int idx = tid; idx < MM*DH; idx += 128) qls[idx] = g_ql[h*MM*DH + idx];
    __syncthreads();
    int t = t0 + tid;
    if (t >= NPAD) return;
    float lg[MM];
    #pragma unroll
    for (int m = 0; m < MM; m++) lg[m] = 0.f;
    #pragma unroll
    for (int d4 = 0; d4 < 16; d4++) {
        float4 k4 = *(const float4*)&ks[tid][d4*4];
        #pragma unroll
        for (int m = 0; m < MM; m++) {
            float4 q4 = *(const float4*)&qls[m*DH + d4*4];
            lg[m] += q4.x*k4.x + q4.y*k4.y + q4.z*k4.z + q4.w*k4.w;
        }
    }
    #pragma unroll
    for (int m = 0; m < MM; m++)
        g_attn3[((size_t)h*MM + m)*NPAD + t] = lg[m];
}

// ---------------- 6b. attn3 softmax normalize ------------------------------------
__global__ void attn3b_kernel() {
    int m = blockIdx.x, h = blockIdx.y;
    int tid = threadIdx.x;
    __shared__ float buf[NPAD];
    __shared__ float red[256];
    float* rowp = g_attn3 + ((size_t)h*MM + m)*NPAD;
    float lmax = -INFINITY;
    for (int t = tid; t < NPAD; t += 256) { float v = rowp[t]; buf[t] = v; lmax = fmaxf(lmax, v); }
    red[tid] = lmax; __syncthreads();
    for (int o = 128; o; o >>= 1) { if (tid < o) red[tid] = fmaxf(red[tid], red[tid+o]); __syncthreads(); }
    float mx = red[0];
    __syncthreads();
    float lsum = 0.f;
    for (int t = tid; t < NPAD; t += 256) { float e = expf(buf[t]-mx); buf[t] = e; lsum += e; }
    red[tid] = lsum; __syncthreads();
    for (int o = 128; o; o >>= 1) { if (tid < o) red[tid] += red[tid+o]; __syncthreads(); }
    float inv = 1.f / red[0];
    for (int t = tid; t < NPAD; t += 256) rowp[t] = buf[t]*inv;
}

// ---------------- 7. av partials ---------------------------------------------------
__global__ __launch_bounds__(544)
void av_kernel() {
    int ch = blockIdx.x, h = blockIdx.y;
    int tid = threadIdx.x;
    int m = tid >> 5, lane = tid & 31;
    int start = ch * 512;
    int end = min(start + 512, NPAD);
    __shared__ float vs[32][QS];
    __shared__ float a3s[MM][32];
    float2 acc = make_float2(0.f, 0.f);
    int nsub = (end - start + 31) >> 5;
    for (int sub = 0; sub < nsub; sub++) {
        int base = start + sub*32;
        if (tid < 512) {
            int row = tid >> 4, c4 = tid & 15;
            int gt = base + row;
            float4 v = (gt < end) ? *(const float4*)&g_qkv[(size_t)gt*QKVD + 1024 + h*DH + c4*4]
                                  : make_float4(0,0,0,0);
            *(float4*)&vs[row][c4*4] = v;
        }
        {
            int mm = tid >> 5, tok = tid & 31;
            int gt = base + tok;
            a3s[mm][tok] = (gt < end) ? g_attn3[((size_t)h*MM + mm)*NPAD + gt] : 0.f;
        }
        __syncthreads();
        #pragma unroll
        for (int tok = 0; tok < 32; tok++) {
            float a = a3s[m][tok];
            float2 v = *(const float2*)&vs[tok][lane*2];
            acc.x += a*v.x; acc.y += a*v.y;
        }
        __syncthreads();
    }
    float* dst = g_avp + ((size_t)(ch*HEADS + h)*MM + m)*DH + lane*2;
    dst[0] = acc.x; dst[1] = acc.y;
}

// ---------------- 8b. out_heads = w1 @ av + conv -> split bf16 ---------------------
#define OTILE 96
__global__ __launch_bounds__(256)
void outh_kernel(const float* __restrict__ conv_w) {
    int h = blockIdx.y;
    int t0 = blockIdx.x * OTILE;
    int tid = threadIdx.x;
    __shared__ float vtile[OTILE+32][DH];
    __shared__ float w1s[OTILE][MM];
    __shared__ float avs[MM*DH];
    __shared__ float cws[KCONV];
    #pragma unroll
    for (int i = 0; i < (OTILE+32)*16/256; i++) {
        int idx = i*256 + tid;
        int row = idx >> 4, c4 = idx & 15;
        int gt = t0 - 16 + row;
        float4 v = (gt >= 0 && gt < NPAD) ? *(const float4*)&g_qkv[(size_t)gt*QKVD + 1024 + h*DH + c4*4]
                                          : make_float4(0,0,0,0);
        *(float4*)&vtile[row][c4*4] = v;
    }
    for (int idx = tid; idx < OTILE*MM; idx += 256) {
        int r = idx / MM, mm = idx % MM;
        int gt = t0 + r;
        w1s[r][mm] = (gt < NPAD) ? g_w1[((size_t)h*NPAD + gt)*MM + mm] : 0.f;
    }
    for (int idx = tid; idx < MM*DH; idx += 256) {
        float s = 0.f;
        #pragma unroll
        for (int c = 0; c < AVCH; c++) s += g_avp[(size_t)(c*HEADS + h)*MM*DH + idx];
        avs[idx] = s;
    }
    if (tid < KCONV) cws[tid] = conv_w[h*KCONV + tid];
    __syncthreads();
    int d = tid & 63, grp = tid >> 6;
    for (int rr = 0; rr < OTILE/4; rr++) {
        int r = grp*(OTILE/4) + rr;
        int t = t0 + r;
        if (t >= NPAD) continue;
        float acc = 0.f;
        #pragma unroll
        for (int mm = 0; mm < MM; mm++) acc += w1s[r][mm]*avs[mm*DH + d];
        #pragma unroll
        for (int k = 0; k < KCONV; k++) acc += cws[k]*vtile[r+k][d];
        size_t idx = (size_t)t*DIM + h*DH + d;
        __nv_bfloat16 bh, bm;
        split2(acc, bh, bm);
        g_oh[idx]=bh; g_om[idx]=bm;
    }
}

// ---------------- 11. attn = w1 @ attn3 (537 MB) ------------------------------------
#define FR 64
__global__ __launch_bounds__(128)
void attn_final_kernel(float* __restrict__ out) {
    int h = blockIdx.z;
    int t0 = blockIdx.y * FR;
    int s = blockIdx.x * 128 + threadIdx.x;
    __shared__ float w1s[FR][20];
    for (int idx = threadIdx.x; idx < FR*MM; idx += 128) {
        int r = idx / MM, m = idx % MM;
        int t = t0 + r;
        w1s[r][m] = (t < NPAD) ? g_w1[((size_t)h*NPAD + t)*MM + m] : 0.f;
    }
    float a3[MM];
    if (s < NPAD) {
        #pragma unroll
        for (int m = 0; m < MM; m++) a3[m] = g_attn3[((size_t)h*MM + m)*NPAD + s];
    }
    __syncthreads();
    if (s >= NPAD) return;
    float* base = out + (size_t)h*ATTN_PER_HEAD + (size_t)t0*NPAD + s;
    int rmax = min(FR, NPAD - t0);
    for (int r = 0; r < rmax; r++) {
        float4 wa = *(const float4*)&w1s[r][0];
        float4 wb = *(const float4*)&w1s[r][4];
        float4 wc = *(const float4*)&w1s[r][8];
        float4 wd = *(const float4*)&w1s[r][12];
        float w16 = w1s[r][16];
        float acc = wa.x*a3[0] + wa.y*a3[1] + wa.z*a3[2] + wa.w*a3[3]
                  + wb.x*a3[4] + wb.y*a3[5] + wb.z*a3[6] + wb.w*a3[7]
                  + wc.x*a3[8] + wc.y*a3[9] + wc.z*a3[10] + wc.w*a3[11]
                  + wd.x*a3[12]+ wd.y*a3[13]+ wd.z*a3[14]+ wd.w*a3[15]
                  + w16*a3[16];
        __stcs(base + (size_t)r*NPAD, acc);
    }
}

// ---------------- launch -------------------------------------------------------------
extern "C" void kernel_launch(void* const* d_in, const int* in_sizes, int n_in,
                              void* d_out, int out_size) {
    const float* x      = (const float*)d_in[0];
    const float* norm_w = (const float*)d_in[1];
    const float* norm_b = (const float*)d_in[2];
    const float* w_qkv  = (const float*)d_in[3];
    const float* w_out  = (const float*)d_in[4];
    const float* b_out  = (const float*)d_in[5];
    const float* conv_w = (const float*)d_in[6];
    float* out = (float*)d_out;

    float* p_qkv;
    cudaGetSymbolAddress((void**)&p_qkv, g_qkv);
    __nv_bfloat16 *p_ah, *p_am, *p_oh, *p_om;
    __nv_bfloat16 *p_wqh, *p_wqm, *p_woh, *p_wom;
    cudaGetSymbolAddress((void**)&p_ah, g_ah);  cudaGetSymbolAddress((void**)&p_am, g_am);
    cudaGetSymbolAddress((void**)&p_oh, g_oh);  cudaGetSymbolAddress((void**)&p_om, g_om);
    cudaGetSymbolAddress((void**)&p_wqh, g_wqh); cudaGetSymbolAddress((void**)&p_wqm, g_wqm);
    cudaGetSymbolAddress((void**)&p_woh, g_woh); cudaGetSymbolAddress((void**)&p_wom, g_wom);

    cudaFuncSetAttribute(gemm_mma, cudaFuncAttributeMaxDynamicSharedMemorySize, GSMEM);

    ln_kernel<<<NPAD, 256>>>(x, norm_w, norm_b);
    wcvt_kernel<<<(QKVD*DIM + 255)/256, 256>>>(w_qkv, p_wqh, p_wqm, QKVD*DIM);
    wcvt_kernel<<<(DIM*DIM + 255)/256, 256>>>(w_out, p_woh, p_wom, DIM*DIM);
    // QKV: [4097,1536] = A[4097,512] @ Wqkv^T (q scaled in epilogue)
    gemm_mma<<<dim3(QKVD/128, (NPAD+127)/128), 256, GSMEM>>>(
        p_ah, p_am, p_wqh, p_wqm, p_qkv, NPAD, QKVD, DIM, 0, nullptr, nullptr);
    landmark_kernel<<<dim3(MM, 2), 512>>>();
    pinv_kernel<<<HEADS, MM*MM>>>();
    attn1w1_kernel<<<dim3((NPAD+127)/128, HEADS), 128>>>();
    attn3a_kernel<<<dim3((NPAD+127)/128, HEADS), 128>>>();
    attn3b_kernel<<<dim3(MM, HEADS), 256>>>();
    av_kernel<<<dim3(AVCH, HEADS), 544>>>();
    outh_kernel<<<dim3((NPAD+OTILE-1)/OTILE, HEADS), 256>>>(conv_w);
    // out-proj: rows 1..4096 of out-heads (skip pad row 0)
    gemm_mma<<<dim3(DIM/128, NTOK/128), 256, GSMEM>>>(
        p_oh + DIM, p_om + DIM, p_woh, p_wom,
        out, NTOK, DIM, DIM, 1, b_out, x);
    attn_final_kernel<<<dim3((NPAD+127)/128, (NPAD+FR-1)/FR, HEADS), 128>>>(out + OUT1_SIZE);
}